// round 15
// baseline (speedup 1.0000x reference)
#include <cuda_runtime.h>
#include <cuda_fp16.h>
#include <math.h>
#include <stdint.h>

// Problem constants
#define BB 4
#define LL 2048
#define GG 2
#define DD 2048
#define HH 16
#define EE 1024          // H*De
#define NN 32768
#define MM (BB*LL)       // 8192 tokens
#define NC 6144          // G*D + D combined GEMM columns
#define GD (GG*DD)       // 4096
#define PAD 9            // (K-1)*DIL

// GEMM tiling
#define KC 64            // K elems per chunk (128 bytes fp16 per row)
#define NCHUNK 16        // single fp16 pass: 16 chunks of 64 = K 1024
#define BUF_BYTES 32768  // A tile 16KB + B tile 16KB
#define SMEM_TOTAL (3 * BUF_BYTES)   // 98304

// ---------------- scratch (static device globals; no allocation) ----------------
__device__ __half g_Ahi[(size_t)MM * EE];
__device__ __half g_Bhi[(size_t)NC * EE];
__device__ float g_vproj[(size_t)MM * DD];   // vproj + bv (only GEMM output stored)
__device__ float g_red[(size_t)MM * 8];      // per token: sk[2], sq[2], sp[2], sv, pad

// ---------------- PTX helpers (plain-sm_103-legal) ----------------
__device__ __forceinline__ uint32_t smem_u32(const void* p) {
    uint32_t a;
    asm("{ .reg .u64 t; cvta.to.shared.u64 t, %1; cvt.u32.u64 %0, t; }" : "=r"(a) : "l"(p));
    return a;
}
__device__ __forceinline__ void cp16(uint32_t dst, const void* src) {
    asm volatile("cp.async.cg.shared.global [%0], [%1], 16;\n" :: "r"(dst), "l"(src));
}
__device__ __forceinline__ void ldsm_x4(uint32_t* r, uint32_t addr) {
    asm volatile("ldmatrix.sync.aligned.m8n8.x4.shared.b16 {%0,%1,%2,%3}, [%4];"
                 : "=r"(r[0]), "=r"(r[1]), "=r"(r[2]), "=r"(r[3]) : "r"(addr));
}
__device__ __forceinline__ void mma_fp16(float* d, const uint32_t* a, const uint32_t* b) {
    asm volatile(
        "mma.sync.aligned.m16n8k16.row.col.f32.f16.f16.f32 "
        "{%0,%1,%2,%3}, {%4,%5,%6,%7}, {%8,%9}, {%0,%1,%2,%3};"
        : "+f"(d[0]), "+f"(d[1]), "+f"(d[2]), "+f"(d[3])
        : "r"(a[0]), "r"(a[1]), "r"(a[2]), "r"(a[3]), "r"(b[0]), "r"(b[1]));
}

__device__ __forceinline__ uint32_t pack2h(float a, float b) {
    return (uint32_t)__half_as_ushort(__float2half_rn(a)) |
           ((uint32_t)__half_as_ushort(__float2half_rn(b)) << 16);
}

// ---------------- 1) merged prep: gather embeddings + weight fp16 conversion ----------------
__global__ void prep_kernel(const int* __restrict__ ids,
                            const float* __restrict__ table,
                            const float* __restrict__ Wk, const float* __restrict__ Wv) {
    int bx = blockIdx.x;
    int t  = threadIdx.x;                // float4 index within 1024-float row
    if (bx < MM) {
        int m = bx;
        if (t < 8) g_red[(size_t)m * 8 + t] = 0.f;
        int h = t >> 4;
        int j = t & 15;
        int row = ids[m * HH + h] + h * NN;
        float4 v = ((const float4*)table)[(size_t)row * 16 + j];
        uint2 hi;
        hi.x = pack2h(v.x, v.y);
        hi.y = pack2h(v.z, v.w);
        ((uint2*)g_Ahi)[(size_t)m * 256 + t] = hi;
    } else {
        int n = bx - MM;
        float4 v = (n < GD) ? ((const float4*)Wk)[(size_t)n * 256 + t]
                            : ((const float4*)Wv)[(size_t)(n - GD) * 256 + t];
        uint2 hi;
        hi.x = pack2h(v.x, v.y);
        hi.y = pack2h(v.z, v.w);
        ((uint2*)g_Bhi)[(size_t)n * 256 + t] = hi;
    }
}

// ---------------- 2) mma.sync fp16 GEMM + fused gate-reduction epilogue ----------------
__global__ __launch_bounds__(128, 2)
void gemm_mma_kernel(const float* __restrict__ hs,
                     const float* __restrict__ bk, const float* __restrict__ bv,
                     const float* __restrict__ n1w, const float* __restrict__ n2w) {
    extern __shared__ char smem[];
    uint32_t sbase = smem_u32(smem);
    int tid = threadIdx.x;
    int lane = tid & 31;
    int wid = tid >> 5;
    int m0 = blockIdx.y * 128;
    int n0 = blockIdx.x * 128;
    int m_w = (wid & 1) * 64;
    int n_w = (wid >> 1) * 64;

    auto issue_loads = [&](int c, int s) {
        int kk = c * KC;
        const char* asrc = (const char*)(g_Ahi + (size_t)(m0 + tid) * EE + kk);
        const char* bsrc = (const char*)(g_Bhi + (size_t)(n0 + tid) * EE + kk);
        uint32_t adst = sbase + s * BUF_BYTES;
        uint32_t bdst = adst + 16384;
#pragma unroll
        for (int q = 0; q < 8; q++) {
            uint32_t off = (uint32_t)tid * 128 + q * 16;
            uint32_t sw = off ^ ((off >> 3) & 0x70);
            cp16(adst + sw, asrc + q * 16);
            cp16(bdst + sw, bsrc + q * 16);
        }
        asm volatile("cp.async.commit_group;\n" ::);
    };

    issue_loads(0, 0);
    issue_loads(1, 1);

    float acc[4][8][4];
#pragma unroll
    for (int i = 0; i < 4; i++)
#pragma unroll
        for (int j = 0; j < 8; j++)
#pragma unroll
            for (int k = 0; k < 4; k++) acc[i][j][k] = 0.f;

    uint32_t arow[4], brow[4];
    uint32_t axorv = (uint32_t)((lane & 7) << 4);
    uint32_t ach = (uint32_t)((lane >> 4) * 16);
#pragma unroll
    for (int mt = 0; mt < 4; mt++)
        arow[mt] = (uint32_t)(m_w + mt * 16 + (lane & 15)) * 128;
    uint32_t bch = (uint32_t)(((lane >> 3) & 1) * 16);
#pragma unroll
    for (int nt = 0; nt < 4; nt++)
        brow[nt] = (uint32_t)(n_w + nt * 16 + ((lane >> 4) & 1) * 8 + (lane & 7)) * 128;

    uint32_t af[2][4][4], bf[2][4][4];

    for (int i = 0; i < NCHUNK; i++) {
        int s = i % 3;
        if (i < NCHUNK - 1) asm volatile("cp.async.wait_group 1;\n" ::);
        else                asm volatile("cp.async.wait_group 0;\n" ::);
        __syncthreads();
        if (i + 2 < NCHUNK) issue_loads(i + 2, (i + 2) % 3);

        uint32_t aBase = sbase + s * BUF_BYTES;
        uint32_t bBase = aBase + 16384;

#pragma unroll
        for (int mt = 0; mt < 4; mt++)
            ldsm_x4(af[0][mt], aBase + arow[mt] + (ach ^ axorv));
#pragma unroll
        for (int nt = 0; nt < 4; nt++)
            ldsm_x4(bf[0][nt], bBase + brow[nt] + (bch ^ axorv));

#pragma unroll
        for (int ks = 0; ks < 4; ks++) {
            int cur = ks & 1, nxt = cur ^ 1;
            if (ks < 3) {
                uint32_t ko = (uint32_t)((ks + 1) * 32);
#pragma unroll
                for (int mt = 0; mt < 4; mt++)
                    ldsm_x4(af[nxt][mt], aBase + arow[mt] + ((ko + ach) ^ axorv));
#pragma unroll
                for (int nt = 0; nt < 4; nt++)
                    ldsm_x4(bf[nxt][nt], bBase + brow[nt] + ((ko + bch) ^ axorv));
            }
#pragma unroll
            for (int mt = 0; mt < 4; mt++)
#pragma unroll
                for (int j = 0; j < 8; j++)
                    mma_fp16(acc[mt][j], af[cur][mt], &bf[cur][j >> 1][(j & 1) * 2]);
        }
    }

    // ---- fused epilogue ----
    int grp = lane >> 2;
    int qd  = lane & 3;
    if (n0 < GD) {
        int g = n0 >> 11;
        float2 bkv[8], wwv[8];
#pragma unroll
        for (int j = 0; j < 8; j++) {
            int col = n0 + n_w + j * 8 + qd * 2;
            bkv[j] = *(const float2*)(bk + col);
            float2 a1 = *(const float2*)(n1w + col);
            float2 a2 = *(const float2*)(n2w + col);
            wwv[j] = make_float2(a1.x * a2.x, a1.y * a2.y);
        }
#pragma unroll
        for (int mt = 0; mt < 4; mt++) {
            int r0 = m0 + m_w + mt * 16 + grp;
            int r1 = r0 + 8;
            const float* h0 = hs + (size_t)r0 * GD + n0 + n_w + qd * 2;
            const float* h1 = hs + (size_t)r1 * GD + n0 + n_w + qd * 2;
            float sk0 = 0, sq0 = 0, sp0 = 0, sk1 = 0, sq1 = 0, sp1 = 0;
#pragma unroll
            for (int j = 0; j < 8; j++) {
                float2 q0 = *(const float2*)(h0 + j * 8);
                float2 q1 = *(const float2*)(h1 + j * 8);
                float kx = acc[mt][j][0] + bkv[j].x;
                float ky = acc[mt][j][1] + bkv[j].y;
                sk0 += kx * kx + ky * ky;
                sq0 += q0.x * q0.x + q0.y * q0.y;
                sp0 += kx * q0.x * wwv[j].x + ky * q0.y * wwv[j].y;
                kx = acc[mt][j][2] + bkv[j].x;
                ky = acc[mt][j][3] + bkv[j].y;
                sk1 += kx * kx + ky * ky;
                sq1 += q1.x * q1.x + q1.y * q1.y;
                sp1 += kx * q1.x * wwv[j].x + ky * q1.y * wwv[j].y;
            }
#pragma unroll
            for (int o = 1; o <= 2; o <<= 1) {
                sk0 += __shfl_xor_sync(0xffffffffu, sk0, o);
                sq0 += __shfl_xor_sync(0xffffffffu, sq0, o);
                sp0 += __shfl_xor_sync(0xffffffffu, sp0, o);
                sk1 += __shfl_xor_sync(0xffffffffu, sk1, o);
                sq1 += __shfl_xor_sync(0xffffffffu, sq1, o);
                sp1 += __shfl_xor_sync(0xffffffffu, sp1, o);
            }
            if (qd == 0) {
                atomicAdd(&g_red[(size_t)r0 * 8 + 0 + g], sk0);
                atomicAdd(&g_red[(size_t)r0 * 8 + 2 + g], sq0);
                atomicAdd(&g_red[(size_t)r0 * 8 + 4 + g], sp0);
                atomicAdd(&g_red[(size_t)r1 * 8 + 0 + g], sk1);
                atomicAdd(&g_red[(size_t)r1 * 8 + 2 + g], sq1);
                atomicAdd(&g_red[(size_t)r1 * 8 + 4 + g], sp1);
            }
        }
    } else {
        int dd = n0 - GD + n_w + qd * 2;
        float2 bvv[8];
#pragma unroll
        for (int j = 0; j < 8; j++) bvv[j] = *(const float2*)(bv + dd + j * 8);
#pragma unroll
        for (int mt = 0; mt < 4; mt++) {
            int r0 = m0 + m_w + mt * 16 + grp;
            int r1 = r0 + 8;
            float* vp0 = g_vproj + (size_t)r0 * DD + dd;
            float* vp1 = g_vproj + (size_t)r1 * DD + dd;
            float sv0 = 0, sv1 = 0;
#pragma unroll
            for (int j = 0; j < 8; j++) {
                float vx = acc[mt][j][0] + bvv[j].x;
                float vy = acc[mt][j][1] + bvv[j].y;
                sv0 += vx * vx + vy * vy;
                *(float2*)(vp0 + j * 8) = make_float2(vx, vy);
                vx = acc[mt][j][2] + bvv[j].x;
                vy = acc[mt][j][3] + bvv[j].y;
                sv1 += vx * vx + vy * vy;
                *(float2*)(vp1 + j * 8) = make_float2(vx, vy);
            }
#pragma unroll
            for (int o = 1; o <= 2; o <<= 1) {
                sv0 += __shfl_xor_sync(0xffffffffu, sv0, o);
                sv1 += __shfl_xor_sync(0xffffffffu, sv1, o);
            }
            if (qd == 0) {
                atomicAdd(&g_red[(size_t)r0 * 8 + 6], sv0);
                atomicAdd(&g_red[(size_t)r1 * 8 + 6], sv1);
            }
        }
    }
}

// ---------------- 3) conv + silu + residual + cache, gate/inv fused in preamble ----------------
// __launch_bounds__(256,5): cap regs at 51 to lift occupancy (R13: time ~ 1/occ
// in this range). Live set in steady loop ~44 regs, so no true spills expected.
__global__ __launch_bounds__(256, 5)
void conv_kernel(const float* __restrict__ cw, const float* __restrict__ scw,
                 float* __restrict__ out, float* __restrict__ cache) {
    __shared__ float4 s_gi[73];          // tokens l0-9 .. l0+63
    int d = (blockIdx.x * 256 + threadIdx.x) * 2;   // d-channel 0..2046, step 2
    int b = blockIdx.z;
    int l0 = blockIdx.y * 64;

    // preamble: compute gate/inv for this block's token window
    if (threadIdx.x < 73) {
        int l = l0 - 9 + (int)threadIdx.x;
        if (l >= 0) {
            int m = b * LL + l;
            const float invD = 1.f / (float)DD;
            const float EPSD = 1.1920929e-07f;
            float svm = g_red[(size_t)m * 8 + 6] * invD;
            float gates[2], invs[2];
#pragma unroll
            for (int g = 0; g < 2; g++) {
                float sk = g_red[(size_t)m * 8 + 0 + g];
                float sq = g_red[(size_t)m * 8 + 2 + g];
                float sp = g_red[(size_t)m * 8 + 4 + g];
                float rk = rsqrtf(sk * invD + EPSD);
                float rq = rsqrtf(sq * invD + EPSD);
                float gp = sp * rk * rq * 0.022097086912079612f;
                float a = sqrtf(fmaxf(fabsf(gp), 1e-6f));
                a = (gp > 0.f) ? a : ((gp < 0.f) ? -a : 0.f);
                float gate = 1.f / (1.f + __expf(-a));
                gates[g] = gate;
                invs[g] = rsqrtf(gate * gate * svm + 1e-5f);
            }
            s_gi[threadIdx.x] = make_float4(gates[0], gates[1], invs[0], invs[1]);
        } else {
            s_gi[threadIdx.x] = make_float4(0.f, 0.f, 0.f, 0.f);
        }
    }
    __syncthreads();

    int c1 = d + DD;                                 // group-1 channel base
    float4 wa0 = *(const float4*)(cw + (size_t)d * 4);
    float4 wa1 = *(const float4*)(cw + (size_t)d * 4 + 4);
    float4 wb0 = *(const float4*)(cw + (size_t)c1 * 4);
    float4 wb1 = *(const float4*)(cw + (size_t)c1 * 4 + 4);
    float2 sc0 = *(const float2*)(scw + d);
    float2 sc1 = *(const float2*)(scw + c1);
    const size_t baseo = ((size_t)b * LL) * GD + d;   // group0; group1 at +DD
    const size_t basev = ((size_t)b * LL) * DD + d;

    auto loadpair = [&](int l, float2& xa, float2& xb) {
        if (l < 0) {
            xa = make_float2(0.f, 0.f);
            xb = make_float2(0.f, 0.f);
            return;
        }
        float4 gi = s_gi[l - (l0 - 9)];
        float2 vp = *(const float2*)(g_vproj + basev + (size_t)l * DD);
        float s0 = gi.x * gi.z, s1 = gi.y * gi.w;       // gate*inv per group
        xa = make_float2(vp.x * s0 * sc0.x, vp.y * s0 * sc0.y);
        xb = make_float2(vp.x * s1 * sc1.x, vp.y * s1 * sc1.y);
    };

#pragma unroll
    for (int r = 0; r < 3; r++) {
        int l = l0 + r;
        float2 a3, a6, a9, b3, b6, b9;
        loadpair(l - 3, a3, b3);
        loadpair(l - 6, a6, b6);
        loadpair(l - 9, a9, b9);
        for (; l < l0 + 64; l += 3) {
            float4 gi = s_gi[l - (l0 - 9)];
            float2 vp = *(const float2*)(g_vproj + basev + (size_t)l * DD);
            float2 v0 = make_float2(vp.x * gi.x, vp.y * gi.x);
            float2 v1 = make_float2(vp.x * gi.y, vp.y * gi.y);
            float2 a0 = make_float2(v0.x * gi.z * sc0.x, v0.y * gi.z * sc0.y);
            float2 b0 = make_float2(v1.x * gi.w * sc1.x, v1.y * gi.w * sc1.y);
            float ya0 = fmaf(wa0.w, a0.x, fmaf(wa0.z, a3.x, fmaf(wa0.y, a6.x, wa0.x * a9.x)));
            float ya1 = fmaf(wa1.w, a0.y, fmaf(wa1.z, a3.y, fmaf(wa1.y, a6.y, wa1.x * a9.y)));
            float yb0 = fmaf(wb0.w, b0.x, fmaf(wb0.z, b3.x, fmaf(wb0.y, b6.x, wb0.x * b9.x)));
            float yb1 = fmaf(wb1.w, b0.y, fmaf(wb1.z, b3.y, fmaf(wb1.y, b6.y, wb1.x * b9.y)));
            ya0 = __fdividef(ya0, 1.f + __expf(-ya0));
            ya1 = __fdividef(ya1, 1.f + __expf(-ya1));
            yb0 = __fdividef(yb0, 1.f + __expf(-yb0));
            yb1 = __fdividef(yb1, 1.f + __expf(-yb1));
            size_t idx = baseo + (size_t)l * GD;
            *(float2*)(out + idx)      = make_float2(v0.x + ya0, v0.y + ya1);
            *(float2*)(out + idx + DD) = make_float2(v1.x + yb0, v1.y + yb1);
            if (l >= LL - PAD) {
                int t = l - (LL - PAD);
                cache[((size_t)b * GD + d + 0) * PAD + t] = a0.x;
                cache[((size_t)b * GD + d + 1) * PAD + t] = a0.y;
                cache[((size_t)b * GD + c1 + 0) * PAD + t] = b0.x;
                cache[((size_t)b * GD + c1 + 1) * PAD + t] = b0.y;
            }
            a9 = a6; a6 = a3; a3 = a0;
            b9 = b6; b6 = b3; b3 = b0;
        }
    }
}

// ---------------- launcher ----------------
extern "C" void kernel_launch(void* const* d_in, const int* in_sizes, int n_in,
                              void* d_out, int out_size) {
    const float* hs    = (const float*)d_in[0];
    const int*   ids   = (const int*)d_in[1];
    const float* table = (const float*)d_in[2];
    const float* Wk    = (const float*)d_in[3];
    const float* bk    = (const float*)d_in[4];
    const float* Wv    = (const float*)d_in[5];
    const float* bv    = (const float*)d_in[6];
    const float* n1w   = (const float*)d_in[7];
    const float* n2w   = (const float*)d_in[8];
    const float* cw    = (const float*)d_in[9];
    const float* scw   = (const float*)d_in[10];
    float* out   = (float*)d_out;
    float* cache = out + (size_t)MM * GD;

    cudaFuncSetAttribute(gemm_mma_kernel,
                         cudaFuncAttributeMaxDynamicSharedMemorySize, SMEM_TOTAL);

    prep_kernel<<<MM + NC, 256>>>(ids, table, Wk, Wv);
    dim3 ggrid(NC / 128, MM / 128);
    gemm_mma_kernel<<<ggrid, 128, SMEM_TOTAL>>>(hs, bk, bv, n1w, n2w);
    dim3 cgrid(DD / 512, LL / 64, BB);
    conv_kernel<<<cgrid, 256>>>(cw, scw, out, cache);
}

// round 16
// speedup vs baseline: 1.8910x; 1.8910x over previous
#include <cuda_runtime.h>
#include <cuda_fp16.h>
#include <math.h>
#include <stdint.h>

// Problem constants
#define BB 4
#define LL 2048
#define GG 2
#define DD 2048
#define HH 16
#define EE 1024          // H*De
#define NN 32768
#define MM (BB*LL)       // 8192 tokens
#define NC 6144          // G*D + D combined GEMM columns
#define GD (GG*DD)       // 4096
#define PAD 9            // (K-1)*DIL

// GEMM tiling
#define KC 64            // K elems per chunk (128 bytes fp16 per row)
#define NCHUNK 16        // single fp16 pass: 16 chunks of 64 = K 1024
#define TILE_BYTES 16384 // one 128x128B swizzled tile
#define STAGE_BYTES 32768 // A tile + B tile
#define SMEM_CTRL (3 * STAGE_BYTES)          // 98304
#define SMEM_TOTAL (SMEM_CTRL + 64)

// ---------------- scratch (static device globals; no allocation) ----------------
// A/B stored as pre-swizzled 16KB tile images: tile (blk, chunk) contiguous.
__device__ unsigned char g_At[(size_t)(MM / 128) * 16 * TILE_BYTES];
__device__ unsigned char g_Bt[(size_t)(NC / 128) * 16 * TILE_BYTES];
__device__ float g_vproj[(size_t)MM * DD];   // vproj + bv (only GEMM output stored)
__device__ float g_red[(size_t)MM * 8];      // per token: sk[2], sq[2], sp[2], sv, pad

// ---------------- PTX helpers (plain sm_90-era, legal on compute_103) ----------------
__device__ __forceinline__ uint32_t smem_u32(const void* p) {
    uint32_t a;
    asm("{ .reg .u64 t; cvta.to.shared.u64 t, %1; cvt.u32.u64 %0, t; }" : "=r"(a) : "l"(p));
    return a;
}
__device__ __forceinline__ void ldsm_x4(uint32_t* r, uint32_t addr) {
    asm volatile("ldmatrix.sync.aligned.m8n8.x4.shared.b16 {%0,%1,%2,%3}, [%4];"
                 : "=r"(r[0]), "=r"(r[1]), "=r"(r[2]), "=r"(r[3]) : "r"(addr));
}
__device__ __forceinline__ void mma_fp16(float* d, const uint32_t* a, const uint32_t* b) {
    asm volatile(
        "mma.sync.aligned.m16n8k16.row.col.f32.f16.f16.f32 "
        "{%0,%1,%2,%3}, {%4,%5,%6,%7}, {%8,%9}, {%0,%1,%2,%3};"
        : "+f"(d[0]), "+f"(d[1]), "+f"(d[2]), "+f"(d[3])
        : "r"(a[0]), "r"(a[1]), "r"(a[2]), "r"(a[3]), "r"(b[0]), "r"(b[1]));
}
__device__ __forceinline__ void mbar_init(uint32_t mbar, uint32_t cnt) {
    asm volatile("mbarrier.init.shared.b64 [%0], %1;" :: "r"(mbar), "r"(cnt) : "memory");
}
__device__ __forceinline__ void mbar_arrive(uint32_t mbar) {
    asm volatile("mbarrier.arrive.shared.b64 _, [%0];" :: "r"(mbar) : "memory");
}
__device__ __forceinline__ void mbar_expect_tx(uint32_t mbar, uint32_t tx) {
    asm volatile("mbarrier.arrive.expect_tx.shared.b64 _, [%0], %1;"
                 :: "r"(mbar), "r"(tx) : "memory");
}
__device__ __forceinline__ void mbar_wait(uint32_t mbar, uint32_t parity) {
    asm volatile(
        "{\n .reg .pred P;\n"
        "WL%=:\n mbarrier.try_wait.parity.shared.b64 P, [%0], %1;\n"
        " @P bra WD%=;\n bra WL%=;\n"
        "WD%=:\n}"
        :: "r"(mbar), "r"(parity) : "memory");
}
__device__ __forceinline__ void bulk_g2s(uint32_t dst, const void* src, uint32_t mbar) {
    asm volatile(
        "cp.async.bulk.shared::cta.global.mbarrier::complete_tx::bytes [%0], [%1], %2, [%3];"
        :: "r"(dst), "l"(src), "r"((uint32_t)TILE_BYTES), "r"(mbar) : "memory");
}

__device__ __forceinline__ uint32_t pack2h(float a, float b) {
    return (uint32_t)__half_as_ushort(__float2half_rn(a)) |
           ((uint32_t)__half_as_ushort(__float2half_rn(b)) << 16);
}

// ---------------- 1) merged prep: gather + weight conversion, into swizzled tiles ----------------
// Thread t of block handles halves [4t, 4t+4) of one 2048B row (token m or W row n).
// Tile image: (blk = idx>>7, chunk = t>>4), byte = (row&127)*128 + (t&15)*8, SW128-swizzled.
__global__ void prep_kernel(const int* __restrict__ ids,
                            const float* __restrict__ table,
                            const float* __restrict__ Wk, const float* __restrict__ Wv) {
    int bx = blockIdx.x;
    int t  = threadIdx.x;                // float4 index within 1024-float row
    int c  = t >> 4;                     // chunk 0..15
    uint32_t boff;
    uint2 hi;
    if (bx < MM) {
        int m = bx;
        if (t < 8) g_red[(size_t)m * 8 + t] = 0.f;
        int h = t >> 4;
        int j = t & 15;
        int row = ids[m * HH + h] + h * NN;
        float4 v = ((const float4*)table)[(size_t)row * 16 + j];
        hi.x = pack2h(v.x, v.y);
        hi.y = pack2h(v.z, v.w);
        boff = (uint32_t)(m & 127) * 128 + (uint32_t)(t & 15) * 8;
        uint32_t sw = boff ^ ((boff >> 3) & 0x70);
        *(uint2*)(g_At + ((size_t)(m >> 7) * 16 + c) * TILE_BYTES + sw) = hi;
    } else {
        int n = bx - MM;
        float4 v = (n < GD) ? ((const float4*)Wk)[(size_t)n * 256 + t]
                            : ((const float4*)Wv)[(size_t)(n - GD) * 256 + t];
        hi.x = pack2h(v.x, v.y);
        hi.y = pack2h(v.z, v.w);
        boff = (uint32_t)(n & 127) * 128 + (uint32_t)(t & 15) * 8;
        uint32_t sw = boff ^ ((boff >> 3) & 0x70);
        *(uint2*)(g_Bt + ((size_t)(n >> 7) * 16 + c) * TILE_BYTES + sw) = hi;
    }
}

// ---------------- 2) bulk-copy fp16 GEMM + fused gate-reduction epilogue ----------------
// 3-stage mbarrier pipeline, single-thread producer issuing cp.async.bulk (2x16KB/chunk);
// no per-chunk __syncthreads. 4 warps, 64x64 each.
__global__ __launch_bounds__(128, 2)
void gemm_mma_kernel(const float* __restrict__ hs,
                     const float* __restrict__ bk, const float* __restrict__ bv,
                     const float* __restrict__ n1w, const float* __restrict__ n2w) {
    extern __shared__ char smem[];
    uint32_t sbase = smem_u32(smem);
    uint32_t mb_full  = sbase + SMEM_CTRL;        // full[0..2] at +0,8,16
    uint32_t mb_empty = sbase + SMEM_CTRL + 24;   // empty[0..2] at +24,32,40
    int tid = threadIdx.x;
    int lane = tid & 31;
    int wid = tid >> 5;
    int m0 = blockIdx.y * 128;
    int n0 = blockIdx.x * 128;
    int m_w = (wid & 1) * 64;
    int n_w = (wid >> 1) * 64;

    if (tid == 0) {
#pragma unroll
        for (int s = 0; s < 3; s++) {
            mbar_init(mb_full + s * 8, 1);
            mbar_init(mb_empty + s * 8, 128);
        }
    }
    __syncthreads();

    const unsigned char* abase = g_At + (size_t)blockIdx.y * 16 * TILE_BYTES;
    const unsigned char* bbase = g_Bt + (size_t)blockIdx.x * 16 * TILE_BYTES;

    // producer: chunk c -> stage c%3; wait empty with parity 1^((c/3)&1)
    auto produce = [&](int c) {
        int s = c % 3;
        uint32_t par = 1u ^ (uint32_t)((c / 3) & 1);
        mbar_wait(mb_empty + s * 8, par);
        mbar_expect_tx(mb_full + s * 8, STAGE_BYTES);
        uint32_t dst = sbase + s * STAGE_BYTES;
        bulk_g2s(dst, abase + (size_t)c * TILE_BYTES, mb_full + s * 8);
        bulk_g2s(dst + TILE_BYTES, bbase + (size_t)c * TILE_BYTES, mb_full + s * 8);
    };

    if (tid == 0) { produce(0); produce(1); }

    float acc[4][8][4];
#pragma unroll
    for (int i = 0; i < 4; i++)
#pragma unroll
        for (int j = 0; j < 8; j++)
#pragma unroll
            for (int k = 0; k < 4; k++) acc[i][j][k] = 0.f;

    uint32_t arow[4], brow[4];
    uint32_t axorv = (uint32_t)((lane & 7) << 4);
    uint32_t ach = (uint32_t)((lane >> 4) * 16);
#pragma unroll
    for (int mt = 0; mt < 4; mt++)
        arow[mt] = (uint32_t)(m_w + mt * 16 + (lane & 15)) * 128;
    uint32_t bch = (uint32_t)(((lane >> 3) & 1) * 16);
#pragma unroll
    for (int nt = 0; nt < 4; nt++)
        brow[nt] = (uint32_t)(n_w + nt * 16 + ((lane >> 4) & 1) * 8 + (lane & 7)) * 128;

    uint32_t af[2][4][4], bf[2][4][4];

    for (int i = 0; i < NCHUNK; i++) {
        int s = i % 3;
        if (tid == 0 && i + 2 < NCHUNK) produce(i + 2);
        // consumer: wait full with parity (i/3)&1
        mbar_wait(mb_full + s * 8, (uint32_t)((i / 3) & 1));

        uint32_t aBase = sbase + s * STAGE_BYTES;
        uint32_t bBase = aBase + TILE_BYTES;

#pragma unroll
        for (int mt = 0; mt < 4; mt++)
            ldsm_x4(af[0][mt], aBase + arow[mt] + (ach ^ axorv));
#pragma unroll
        for (int nt = 0; nt < 4; nt++)
            ldsm_x4(bf[0][nt], bBase + brow[nt] + (bch ^ axorv));

#pragma unroll
        for (int ks = 0; ks < 4; ks++) {
            int cur = ks & 1, nxt = cur ^ 1;
            if (ks < 3) {
                uint32_t ko = (uint32_t)((ks + 1) * 32);
#pragma unroll
                for (int mt = 0; mt < 4; mt++)
                    ldsm_x4(af[nxt][mt], aBase + arow[mt] + ((ko + ach) ^ axorv));
#pragma unroll
                for (int nt = 0; nt < 4; nt++)
                    ldsm_x4(bf[nxt][nt], bBase + brow[nt] + ((ko + bch) ^ axorv));
            }
#pragma unroll
            for (int mt = 0; mt < 4; mt++)
#pragma unroll
                for (int j = 0; j < 8; j++)
                    mma_fp16(acc[mt][j], af[cur][mt], &bf[cur][j >> 1][(j & 1) * 2]);
        }
        mbar_arrive(mb_empty + s * 8);   // stage free for reuse
    }

    // ---- fused epilogue (unchanged from R14) ----
    int grp = lane >> 2;
    int qd  = lane & 3;
    if (n0 < GD) {
        int g = n0 >> 11;
        float2 bkv[8], wwv[8];
#pragma unroll
        for (int j = 0; j < 8; j++) {
            int col = n0 + n_w + j * 8 + qd * 2;
            bkv[j] = *(const float2*)(bk + col);
            float2 a1 = *(const float2*)(n1w + col);
            float2 a2 = *(const float2*)(n2w + col);
            wwv[j] = make_float2(a1.x * a2.x, a1.y * a2.y);
        }
#pragma unroll
        for (int mt = 0; mt < 4; mt++) {
            int r0 = m0 + m_w + mt * 16 + grp;
            int r1 = r0 + 8;
            const float* h0 = hs + (size_t)r0 * GD + n0 + n_w + qd * 2;
            const float* h1 = hs + (size_t)r1 * GD + n0 + n_w + qd * 2;
            float sk0 = 0, sq0 = 0, sp0 = 0, sk1 = 0, sq1 = 0, sp1 = 0;
#pragma unroll
            for (int j = 0; j < 8; j++) {
                float2 q0 = *(const float2*)(h0 + j * 8);
                float2 q1 = *(const float2*)(h1 + j * 8);
                float kx = acc[mt][j][0] + bkv[j].x;
                float ky = acc[mt][j][1] + bkv[j].y;
                sk0 += kx * kx + ky * ky;
                sq0 += q0.x * q0.x + q0.y * q0.y;
                sp0 += kx * q0.x * wwv[j].x + ky * q0.y * wwv[j].y;
                kx = acc[mt][j][2] + bkv[j].x;
                ky = acc[mt][j][3] + bkv[j].y;
                sk1 += kx * kx + ky * ky;
                sq1 += q1.x * q1.x + q1.y * q1.y;
                sp1 += kx * q1.x * wwv[j].x + ky * q1.y * wwv[j].y;
            }
#pragma unroll
            for (int o = 1; o <= 2; o <<= 1) {
                sk0 += __shfl_xor_sync(0xffffffffu, sk0, o);
                sq0 += __shfl_xor_sync(0xffffffffu, sq0, o);
                sp0 += __shfl_xor_sync(0xffffffffu, sp0, o);
                sk1 += __shfl_xor_sync(0xffffffffu, sk1, o);
                sq1 += __shfl_xor_sync(0xffffffffu, sq1, o);
                sp1 += __shfl_xor_sync(0xffffffffu, sp1, o);
            }
            if (qd == 0) {
                atomicAdd(&g_red[(size_t)r0 * 8 + 0 + g], sk0);
                atomicAdd(&g_red[(size_t)r0 * 8 + 2 + g], sq0);
                atomicAdd(&g_red[(size_t)r0 * 8 + 4 + g], sp0);
                atomicAdd(&g_red[(size_t)r1 * 8 + 0 + g], sk1);
                atomicAdd(&g_red[(size_t)r1 * 8 + 2 + g], sq1);
                atomicAdd(&g_red[(size_t)r1 * 8 + 4 + g], sp1);
            }
        }
    } else {
        int dd = n0 - GD + n_w + qd * 2;
        float2 bvv[8];
#pragma unroll
        for (int j = 0; j < 8; j++) bvv[j] = *(const float2*)(bv + dd + j * 8);
#pragma unroll
        for (int mt = 0; mt < 4; mt++) {
            int r0 = m0 + m_w + mt * 16 + grp;
            int r1 = r0 + 8;
            float* vp0 = g_vproj + (size_t)r0 * DD + dd;
            float* vp1 = g_vproj + (size_t)r1 * DD + dd;
            float sv0 = 0, sv1 = 0;
#pragma unroll
            for (int j = 0; j < 8; j++) {
                float vx = acc[mt][j][0] + bvv[j].x;
                float vy = acc[mt][j][1] + bvv[j].y;
                sv0 += vx * vx + vy * vy;
                *(float2*)(vp0 + j * 8) = make_float2(vx, vy);
                vx = acc[mt][j][2] + bvv[j].x;
                vy = acc[mt][j][3] + bvv[j].y;
                sv1 += vx * vx + vy * vy;
                *(float2*)(vp1 + j * 8) = make_float2(vx, vy);
            }
#pragma unroll
            for (int o = 1; o <= 2; o <<= 1) {
                sv0 += __shfl_xor_sync(0xffffffffu, sv0, o);
                sv1 += __shfl_xor_sync(0xffffffffu, sv1, o);
            }
            if (qd == 0) {
                atomicAdd(&g_red[(size_t)r0 * 8 + 6], sv0);
                atomicAdd(&g_red[(size_t)r1 * 8 + 6], sv1);
            }
        }
    }
}

// ---------------- 3) conv + silu + residual + cache (R14-proven, no reg cap) ----------------
__global__ __launch_bounds__(256)
void conv_kernel(const float* __restrict__ cw, const float* __restrict__ scw,
                 float* __restrict__ out, float* __restrict__ cache) {
    __shared__ float4 s_gi[73];          // tokens l0-9 .. l0+63
    int d = (blockIdx.x * 256 + threadIdx.x) * 2;   // d-channel 0..2046, step 2
    int b = blockIdx.z;
    int l0 = blockIdx.y * 64;

    if (threadIdx.x < 73) {
        int l = l0 - 9 + (int)threadIdx.x;
        if (l >= 0) {
            int m = b * LL + l;
            const float invD = 1.f / (float)DD;
            const float EPSD = 1.1920929e-07f;
            float svm = g_red[(size_t)m * 8 + 6] * invD;
            float gates[2], invs[2];
#pragma unroll
            for (int g = 0; g < 2; g++) {
                float sk = g_red[(size_t)m * 8 + 0 + g];
                float sq = g_red[(size_t)m * 8 + 2 + g];
                float sp = g_red[(size_t)m * 8 + 4 + g];
                float rk = rsqrtf(sk * invD + EPSD);
                float rq = rsqrtf(sq * invD + EPSD);
                float gp = sp * rk * rq * 0.022097086912079612f;
                float a = sqrtf(fmaxf(fabsf(gp), 1e-6f));
                a = (gp > 0.f) ? a : ((gp < 0.f) ? -a : 0.f);
                float gate = 1.f / (1.f + __expf(-a));
                gates[g] = gate;
                invs[g] = rsqrtf(gate * gate * svm + 1e-5f);
            }
            s_gi[threadIdx.x] = make_float4(gates[0], gates[1], invs[0], invs[1]);
        } else {
            s_gi[threadIdx.x] = make_float4(0.f, 0.f, 0.f, 0.f);
        }
    }
    __syncthreads();

    int c1 = d + DD;                                 // group-1 channel base
    float4 wa0 = *(const float4*)(cw + (size_t)d * 4);
    float4 wa1 = *(const float4*)(cw + (size_t)d * 4 + 4);
    float4 wb0 = *(const float4*)(cw + (size_t)c1 * 4);
    float4 wb1 = *(const float4*)(cw + (size_t)c1 * 4 + 4);
    float2 sc0 = *(const float2*)(scw + d);
    float2 sc1 = *(const float2*)(scw + c1);
    const size_t baseo = ((size_t)b * LL) * GD + d;   // group0; group1 at +DD
    const size_t basev = ((size_t)b * LL) * DD + d;

    auto loadpair = [&](int l, float2& xa, float2& xb) {
        if (l < 0) {
            xa = make_float2(0.f, 0.f);
            xb = make_float2(0.f, 0.f);
            return;
        }
        float4 gi = s_gi[l - (l0 - 9)];
        float2 vp = *(const float2*)(g_vproj + basev + (size_t)l * DD);
        float s0 = gi.x * gi.z, s1 = gi.y * gi.w;       // gate*inv per group
        xa = make_float2(vp.x * s0 * sc0.x, vp.y * s0 * sc0.y);
        xb = make_float2(vp.x * s1 * sc1.x, vp.y * s1 * sc1.y);
    };

#pragma unroll
    for (int r = 0; r < 3; r++) {
        int l = l0 + r;
        float2 a3, a6, a9, b3, b6, b9;
        loadpair(l - 3, a3, b3);
        loadpair(l - 6, a6, b6);
        loadpair(l - 9, a9, b9);
        for (; l < l0 + 64; l += 3) {
            float4 gi = s_gi[l - (l0 - 9)];
            float2 vp = *(const float2*)(g_vproj + basev + (size_t)l * DD);
            float2 v0 = make_float2(vp.x * gi.x, vp.y * gi.x);
            float2 v1 = make_float2(vp.x * gi.y, vp.y * gi.y);
            float2 a0 = make_float2(v0.x * gi.z * sc0.x, v0.y * gi.z * sc0.y);
            float2 b0 = make_float2(v1.x * gi.w * sc1.x, v1.y * gi.w * sc1.y);
            float ya0 = fmaf(wa0.w, a0.x, fmaf(wa0.z, a3.x, fmaf(wa0.y, a6.x, wa0.x * a9.x)));
            float ya1 = fmaf(wa1.w, a0.y, fmaf(wa1.z, a3.y, fmaf(wa1.y, a6.y, wa1.x * a9.y)));
            float yb0 = fmaf(wb0.w, b0.x, fmaf(wb0.z, b3.x, fmaf(wb0.y, b6.x, wb0.x * b9.x)));
            float yb1 = fmaf(wb1.w, b0.y, fmaf(wb1.z, b3.y, fmaf(wb1.y, b6.y, wb1.x * b9.y)));
            ya0 = __fdividef(ya0, 1.f + __expf(-ya0));
            ya1 = __fdividef(ya1, 1.f + __expf(-ya1));
            yb0 = __fdividef(yb0, 1.f + __expf(-yb0));
            yb1 = __fdividef(yb1, 1.f + __expf(-yb1));
            size_t idx = baseo + (size_t)l * GD;
            *(float2*)(out + idx)      = make_float2(v0.x + ya0, v0.y + ya1);
            *(float2*)(out + idx + DD) = make_float2(v1.x + yb0, v1.y + yb1);
            if (l >= LL - PAD) {
                int t = l - (LL - PAD);
                cache[((size_t)b * GD + d + 0) * PAD + t] = a0.x;
                cache[((size_t)b * GD + d + 1) * PAD + t] = a0.y;
                cache[((size_t)b * GD + c1 + 0) * PAD + t] = b0.x;
                cache[((size_t)b * GD + c1 + 1) * PAD + t] = b0.y;
            }
            a9 = a6; a6 = a3; a3 = a0;
            b9 = b6; b6 = b3; b3 = b0;
        }
    }
}

// ---------------- launcher ----------------
extern "C" void kernel_launch(void* const* d_in, const int* in_sizes, int n_in,
                              void* d_out, int out_size) {
    const float* hs    = (const float*)d_in[0];
    const int*   ids   = (const int*)d_in[1];
    const float* table = (const float*)d_in[2];
    const float* Wk    = (const float*)d_in[3];
    const float* bk    = (const float*)d_in[4];
    const float* Wv    = (const float*)d_in[5];
    const float* bv    = (const float*)d_in[6];
    const float* n1w   = (const float*)d_in[7];
    const float* n2w   = (const float*)d_in[8];
    const float* cw    = (const float*)d_in[9];
    const float* scw   = (const float*)d_in[10];
    float* out   = (float*)d_out;
    float* cache = out + (size_t)MM * GD;

    cudaFuncSetAttribute(gemm_mma_kernel,
                         cudaFuncAttributeMaxDynamicSharedMemorySize, SMEM_TOTAL);

    prep_kernel<<<MM + NC, 256>>>(ids, table, Wk, Wv);
    dim3 ggrid(NC / 128, MM / 128);
    gemm_mma_kernel<<<ggrid, 128, SMEM_TOTAL>>>(hs, bk, bv, n1w, n2w);
    dim3 cgrid(DD / 512, LL / 64, BB);
    conv_kernel<<<cgrid, 256>>>(cw, scw, out, cache);
}